// round 1
// baseline (speedup 1.0000x reference)
#include <cuda_runtime.h>
#include <cuda_bf16.h>
#include <math.h>

// Problem constants
#define S       4096
#define Hdim    2880
#define NQ      64
#define NKV     8
#define HD      64
#define Wwin    128
#define QKV_N   5120          // (NQ + 2*NKV) * HD
#define ATTN_N  4096          // NQ * HD
#define SCALE   0.125f        // HD^-0.5

// Scratch (device globals: allowed; no dynamic allocation)
__device__ float g_qkv[S * QKV_N];    // 84 MB
__device__ float g_attn[S * ATTN_N];  // 67 MB

// ---------------------------------------------------------------------------
// GEMM: C[M,N] = A[M,K] @ B[K,N] + bias[N]   (all row-major fp32)
// BM=128, BN=64, BK=16, 256 threads, 8x4 register tile per thread.
// Requires: M%128==0, N%64==0, K%16==0 (true for both GEMMs here).
// ---------------------------------------------------------------------------
#define BM 128
#define BN 64
#define BK 16

__global__ __launch_bounds__(256) void gemm_bias_kernel(
    const float* __restrict__ A, const float* __restrict__ B,
    const float* __restrict__ bias, float* __restrict__ C,
    int M, int N, int K)
{
    __shared__ float As[BK][BM];
    __shared__ float Bs[BK][BN];

    const int tid = threadIdx.x;
    const int m0 = blockIdx.y * BM;
    const int n0 = blockIdx.x * BN;
    const int ty = tid >> 4;   // 0..15
    const int tx = tid & 15;   // 0..15

    float acc[8][4];
    #pragma unroll
    for (int i = 0; i < 8; ++i)
        #pragma unroll
        for (int j = 0; j < 4; ++j) acc[i][j] = 0.f;

    for (int k0 = 0; k0 < K; k0 += BK) {
        // Load A tile (128x16) as float4, store transposed As[k][m]
        #pragma unroll
        for (int i = 0; i < 2; ++i) {
            int id  = tid * 2 + i;        // 0..511
            int row = id >> 2;            // 0..127
            int c4  = id & 3;             // 0..3
            float4 v = *(const float4*)(A + (size_t)(m0 + row) * K + k0 + c4 * 4);
            As[c4 * 4 + 0][row] = v.x;
            As[c4 * 4 + 1][row] = v.y;
            As[c4 * 4 + 2][row] = v.z;
            As[c4 * 4 + 3][row] = v.w;
        }
        // Load B tile (16x64) as float4
        {
            int row = tid >> 4;           // 0..15
            int c4  = tid & 15;           // 0..15
            *(float4*)(&Bs[row][c4 * 4]) =
                *(const float4*)(B + (size_t)(k0 + row) * N + n0 + c4 * 4);
        }
        __syncthreads();

        #pragma unroll
        for (int k = 0; k < BK; ++k) {
            float ra[8], rb[4];
            #pragma unroll
            for (int i = 0; i < 8; ++i) ra[i] = As[k][ty * 8 + i];
            #pragma unroll
            for (int j = 0; j < 4; ++j) rb[j] = Bs[k][tx * 4 + j];
            #pragma unroll
            for (int i = 0; i < 8; ++i)
                #pragma unroll
                for (int j = 0; j < 4; ++j)
                    acc[i][j] += ra[i] * rb[j];
        }
        __syncthreads();
    }

    float4 bb = *(const float4*)(bias + n0 + tx * 4);
    #pragma unroll
    for (int i = 0; i < 8; ++i) {
        float4 out;
        out.x = acc[i][0] + bb.x;
        out.y = acc[i][1] + bb.y;
        out.z = acc[i][2] + bb.z;
        out.w = acc[i][3] + bb.w;
        *(float4*)(C + (size_t)(m0 + ty * 8 + i) * N + n0 + tx * 4) = out;
    }
}

// ---------------------------------------------------------------------------
// RoPE in-place on q (heads 0..63) and k (heads 64..71) of g_qkv.
// rotate_half: out[d]     = x[d]*cos[d]     - x[d+32]*sin[d]      (d < 32)
//              out[d+32]  = x[d+32]*cos[d+32] + x[d]*sin[d+32]
// One thread per (s, head, d<32).
// ---------------------------------------------------------------------------
__global__ void rope_kernel(float* __restrict__ qkv,
                            const float* __restrict__ cosb,
                            const float* __restrict__ sinb)
{
    int idx = blockIdx.x * blockDim.x + threadIdx.x;
    const int total = S * (NQ + NKV) * 32;
    if (idx >= total) return;
    int d = idx & 31;
    int rem = idx >> 5;
    int h = rem % (NQ + NKV);
    int s = rem / (NQ + NKV);

    float* row = qkv + (size_t)s * QKV_N + h * HD;
    float c0 = cosb[s * HD + d];
    float s0 = sinb[s * HD + d];
    float c1 = cosb[s * HD + d + 32];
    float s1 = sinb[s * HD + d + 32];
    float x0 = row[d];
    float x1 = row[d + 32];
    row[d]      = x0 * c0 - x1 * s0;
    row[d + 32] = x1 * c1 + x0 * s1;
}

// ---------------------------------------------------------------------------
// Sliding-window attention with sink logits.
// Grid: (NQ heads, S/W blocks). 128 threads = 1 query each.
// Each query at abs pos p attends keys (p-127 .. p]: within the 2-block
// concatenated window [prev block | cur block], chunk0 needs j>qi, chunk1 j<=qi.
// Keys streamed in 64-row sub-chunks through 32KB static smem.
// Online softmax seeded with the sink: m = sink, l = 1, o = 0.
// ---------------------------------------------------------------------------
__global__ __launch_bounds__(128) void attn_kernel(
    const float* __restrict__ qkv,
    const float* __restrict__ sinks,
    float* __restrict__ attn_out)
{
    __shared__ float sK[64 * HD];
    __shared__ float sV[64 * HD];

    const int h  = blockIdx.x;        // q head 0..63
    const int bi = blockIdx.y;        // query block 0..31
    const int n  = h >> 3;            // kv head
    const int qi = threadIdx.x;       // query within block, 0..127

    // Load q row into registers
    float q[HD];
    {
        const float4* qsrc = (const float4*)(qkv + (size_t)(bi * Wwin + qi) * QKV_N + h * HD);
        #pragma unroll
        for (int i = 0; i < HD / 4; ++i) {
            float4 v = qsrc[i];
            q[i * 4 + 0] = v.x; q[i * 4 + 1] = v.y;
            q[i * 4 + 2] = v.z; q[i * 4 + 3] = v.w;
        }
    }

    float m = sinks[h];
    float l = 1.f;
    float o[HD];
    #pragma unroll
    for (int d = 0; d < HD; ++d) o[d] = 0.f;

    for (int sc = 0; sc < 4; ++sc) {
        const int c  = sc >> 1;              // 0 = previous block, 1 = current
        const int kb = bi - 1 + c;           // source block for this sub-chunk
        if (kb < 0) continue;                // uniform across CTA (bi uniform)
        const int jb = (sc & 1) * 64;        // row offset within source block

        __syncthreads();
        // Load 64 K rows + 64 V rows (float4-vectorized, coalesced)
        for (int i = threadIdx.x; i < 64 * (HD / 4); i += 128) {
            int r  = i >> 4;                 // key row 0..63
            int d4 = i & 15;                 // float4 within row
            size_t base = (size_t)(kb * Wwin + jb + r) * QKV_N + n * HD + d4 * 4;
            ((float4*)sK)[i] = *(const float4*)(qkv + base + NQ * HD);            // K region
            ((float4*)sV)[i] = *(const float4*)(qkv + base + (NQ + NKV) * HD);    // V region
        }
        __syncthreads();

        int jlo, jhi;
        if (c == 0) { jlo = qi + 1 - jb; if (jlo < 0) jlo = 0; jhi = 64; }
        else        { jlo = 0; jhi = qi + 1 - jb; if (jhi > 64) jhi = 64; if (jhi < 0) jhi = 0; }

        for (int j = jlo; j < jhi; ++j) {
            float sdot = 0.f;
            const float* krow = sK + j * HD;
            #pragma unroll
            for (int d = 0; d < HD; ++d) sdot += q[d] * krow[d];
            sdot *= SCALE;

            float mnew  = fmaxf(m, sdot);
            float corr  = __expf(m - mnew);
            float p     = __expf(sdot - mnew);
            l = l * corr + p;
            const float* vrow = sV + j * HD;
            #pragma unroll
            for (int d = 0; d < HD; ++d) o[d] = o[d] * corr + p * vrow[d];
            m = mnew;
        }
    }

    float inv = 1.f / l;
    float4* dst = (float4*)(attn_out + (size_t)(bi * Wwin + qi) * ATTN_N + h * HD);
    #pragma unroll
    for (int i = 0; i < HD / 4; ++i) {
        float4 v;
        v.x = o[i * 4 + 0] * inv; v.y = o[i * 4 + 1] * inv;
        v.z = o[i * 4 + 2] * inv; v.w = o[i * 4 + 3] * inv;
        dst[i] = v;
    }
}

// ---------------------------------------------------------------------------
// Launch
// ---------------------------------------------------------------------------
extern "C" void kernel_launch(void* const* d_in, const int* in_sizes, int n_in,
                              void* d_out, int out_size)
{
    const float* hidden = (const float*)d_in[0];
    const float* cosb   = (const float*)d_in[1];
    const float* sinb   = (const float*)d_in[2];
    const float* w_qkv  = (const float*)d_in[3];
    const float* b_qkv  = (const float*)d_in[4];
    const float* w_o    = (const float*)d_in[5];
    const float* b_o    = (const float*)d_in[6];
    const float* sinks  = (const float*)d_in[7];
    float* out = (float*)d_out;

    float *qkv, *attn;
    cudaGetSymbolAddress((void**)&qkv,  g_qkv);
    cudaGetSymbolAddress((void**)&attn, g_attn);

    // 1) QKV projection: [4096,2880] @ [2880,5120] + bias
    {
        dim3 grid(QKV_N / BN, S / BM);
        gemm_bias_kernel<<<grid, 256>>>(hidden, w_qkv, b_qkv, qkv, S, QKV_N, Hdim);
    }
    // 2) RoPE on q + k
    {
        int total = S * (NQ + NKV) * 32;
        rope_kernel<<<(total + 255) / 256, 256>>>(qkv, cosb, sinb);
    }
    // 3) Sliding-window attention with sinks
    {
        dim3 grid(NQ, S / Wwin);
        attn_kernel<<<grid, 128>>>(qkv, sinks, attn);
    }
    // 4) Output projection: [4096,4096] @ [4096,2880] + bias
    {
        dim3 grid(Hdim / BN, S / BM);
        gemm_bias_kernel<<<grid, 256>>>(attn, w_o, b_o, out, S, Hdim, ATTN_N);
    }
}

// round 2
// speedup vs baseline: 1.2309x; 1.2309x over previous
#include <cuda_runtime.h>
#include <cuda_bf16.h>
#include <math.h>
#include <stdint.h>

// Problem constants
#define S       4096
#define Hdim    2880
#define NQ      64
#define NKV     8
#define HD      64
#define Wwin    128
#define QKV_N   5120          // (NQ + 2*NKV) * HD
#define ATTN_N  4096          // NQ * HD
#define SCALE   0.125f        // HD^-0.5

// Scratch
__device__ float g_qkv[S * QKV_N];    // 84 MB
__device__ float g_attn[S * ATTN_N];  // 67 MB

// ---------------------------------------------------------------------------
// TF32 tensor-core GEMM with 3-term precision split (fp32-accurate).
// C[M,N] = A[M,K] @ B[K,N] + bias[N], row-major fp32.
// CTA tile 128x64, BK=16, 256 threads = 8 warps (4m x 2n), warp tile 32x32.
// mma.sync.aligned.m16n8k8.row.col.f32.tf32.tf32.f32
// Requires M%128==0, N%64==0, K%16==0.
// ---------------------------------------------------------------------------
#define BM 128
#define BN 64
#define BK 16
#define SA 20   // As row stride (floats): banks (20m+k)%32 all distinct -> conflict-free
#define SB 68   // Bs row stride (floats): banks (4k+n)%32 all distinct -> conflict-free

__device__ __forceinline__ void split_tf32(float x, uint32_t& hi, uint32_t& lo) {
    uint32_t h;
    asm("cvt.rna.tf32.f32 %0, %1;" : "=r"(h) : "f"(x));
    float r = x - __uint_as_float(h);
    asm("cvt.rna.tf32.f32 %0, %1;" : "=r"(lo) : "f"(r));
    hi = h;
}

__device__ __forceinline__ void mma_tf32(float c[4], const uint32_t a[4], const uint32_t b[2]) {
    asm volatile(
        "mma.sync.aligned.m16n8k8.row.col.f32.tf32.tf32.f32 "
        "{%0,%1,%2,%3}, {%4,%5,%6,%7}, {%8,%9}, {%0,%1,%2,%3};\n"
        : "+f"(c[0]), "+f"(c[1]), "+f"(c[2]), "+f"(c[3])
        : "r"(a[0]), "r"(a[1]), "r"(a[2]), "r"(a[3]), "r"(b[0]), "r"(b[1]));
}

__global__ __launch_bounds__(256, 1) void gemm_tf32_kernel(
    const float* __restrict__ A, const float* __restrict__ B,
    const float* __restrict__ bias, float* __restrict__ C,
    int M, int N, int K)
{
    __shared__ float sA[2][BM * SA];   // [m][k], stride SA
    __shared__ float sB[2][BK * SB];   // [k][n], stride SB

    const int tid  = threadIdx.x;
    const int lane = tid & 31;
    const int wid  = tid >> 5;
    const int wm   = wid >> 1;          // 0..3
    const int wn   = wid & 1;           // 0..1
    const int m0   = blockIdx.y * BM;
    const int n0   = blockIdx.x * BN;

    const int lr = lane >> 2;           // 0..7
    const int lc = lane & 3;            // 0..3

    float acc[2][4][4];
    #pragma unroll
    for (int i = 0; i < 2; ++i)
        #pragma unroll
        for (int j = 0; j < 4; ++j)
            #pragma unroll
            for (int e = 0; e < 4; ++e) acc[i][j][e] = 0.f;

    const int NC = K / BK;

    // staging registers: A 2 float4, B 1 float4
    float4 stA[2], stB;
    // A tile: 128 rows x 4 float4 = 512 -> 2 per thread
    int arow[2], ac4[2];
    #pragma unroll
    for (int l = 0; l < 2; ++l) {
        int idx = tid + l * 256;
        arow[l] = idx >> 2;             // 0..127
        ac4[l]  = idx & 3;              // 0..3
    }
    // B tile: 16 rows x 16 float4 = 256 -> 1 per thread
    const int brow = tid >> 4;          // 0..15
    const int bc4  = tid & 15;          // 0..15

    // prologue: load chunk 0 -> smem[0]
    #pragma unroll
    for (int l = 0; l < 2; ++l)
        stA[l] = *(const float4*)(A + (size_t)(m0 + arow[l]) * K + ac4[l] * 4);
    stB = *(const float4*)(B + (size_t)brow * N + n0 + bc4 * 4);
    #pragma unroll
    for (int l = 0; l < 2; ++l) {
        sA[0][arow[l] * SA + ac4[l] * 4 + 0] = stA[l].x;
        sA[0][arow[l] * SA + ac4[l] * 4 + 1] = stA[l].y;
        sA[0][arow[l] * SA + ac4[l] * 4 + 2] = stA[l].z;
        sA[0][arow[l] * SA + ac4[l] * 4 + 3] = stA[l].w;
    }
    sB[0][brow * SB + bc4 * 4 + 0] = stB.x;
    sB[0][brow * SB + bc4 * 4 + 1] = stB.y;
    sB[0][brow * SB + bc4 * 4 + 2] = stB.z;
    sB[0][brow * SB + bc4 * 4 + 3] = stB.w;
    __syncthreads();

    int buf = 0;
    for (int ch = 0; ch < NC; ++ch) {
        // prefetch next chunk into registers
        if (ch + 1 < NC) {
            int k0 = (ch + 1) * BK;
            #pragma unroll
            for (int l = 0; l < 2; ++l)
                stA[l] = *(const float4*)(A + (size_t)(m0 + arow[l]) * K + k0 + ac4[l] * 4);
            stB = *(const float4*)(B + (size_t)(k0 + brow) * N + n0 + bc4 * 4);
        }

        // compute on smem[buf]
        const float* As = sA[buf];
        const float* Bs = sB[buf];
        #pragma unroll
        for (int ks = 0; ks < BK / 8; ++ks) {
            const int kk = ks * 8;
            uint32_t ah[2][4], al[2][4], bh[4][2], bl[4][2];
            #pragma unroll
            for (int i = 0; i < 2; ++i) {
                int r = wm * 32 + i * 16 + lr;
                int c = kk + lc;
                split_tf32(As[r * SA + c],           ah[i][0], al[i][0]);
                split_tf32(As[(r + 8) * SA + c],     ah[i][1], al[i][1]);
                split_tf32(As[r * SA + c + 4],       ah[i][2], al[i][2]);
                split_tf32(As[(r + 8) * SA + c + 4], ah[i][3], al[i][3]);
            }
            #pragma unroll
            for (int j = 0; j < 4; ++j) {
                int cc = wn * 32 + j * 8 + lr;
                int rr = kk + lc;
                split_tf32(Bs[rr * SB + cc],       bh[j][0], bl[j][0]);
                split_tf32(Bs[(rr + 4) * SB + cc], bh[j][1], bl[j][1]);
            }
            #pragma unroll
            for (int i = 0; i < 2; ++i)
                #pragma unroll
                for (int j = 0; j < 4; ++j) {
                    mma_tf32(acc[i][j], ah[i], bh[j]);
                    mma_tf32(acc[i][j], ah[i], bl[j]);
                    mma_tf32(acc[i][j], al[i], bh[j]);
                }
        }

        // store prefetched chunk into other buffer
        if (ch + 1 < NC) {
            int nb = buf ^ 1;
            #pragma unroll
            for (int l = 0; l < 2; ++l) {
                sA[nb][arow[l] * SA + ac4[l] * 4 + 0] = stA[l].x;
                sA[nb][arow[l] * SA + ac4[l] * 4 + 1] = stA[l].y;
                sA[nb][arow[l] * SA + ac4[l] * 4 + 2] = stA[l].z;
                sA[nb][arow[l] * SA + ac4[l] * 4 + 3] = stA[l].w;
            }
            sB[nb][brow * SB + bc4 * 4 + 0] = stB.x;
            sB[nb][brow * SB + bc4 * 4 + 1] = stB.y;
            sB[nb][brow * SB + bc4 * 4 + 2] = stB.z;
            sB[nb][brow * SB + bc4 * 4 + 3] = stB.w;
            __syncthreads();
            buf = nb;
        }
    }

    // epilogue: bias + store (float2 per c-pair)
    #pragma unroll
    for (int i = 0; i < 2; ++i) {
        int row = m0 + wm * 32 + i * 16 + lr;
        #pragma unroll
        for (int j = 0; j < 4; ++j) {
            int col = n0 + wn * 32 + j * 8 + 2 * lc;
            float b0 = bias[col], b1 = bias[col + 1];
            float2 v0 = make_float2(acc[i][j][0] + b0, acc[i][j][1] + b1);
            float2 v1 = make_float2(acc[i][j][2] + b0, acc[i][j][3] + b1);
            *(float2*)(C + (size_t)row * N + col)       = v0;
            *(float2*)(C + (size_t)(row + 8) * N + col) = v1;
        }
    }
}

// ---------------------------------------------------------------------------
// RoPE in-place on q (heads 0..63) and k (heads 64..71).
// ---------------------------------------------------------------------------
__global__ void rope_kernel(float* __restrict__ qkv,
                            const float* __restrict__ cosb,
                            const float* __restrict__ sinb)
{
    int idx = blockIdx.x * blockDim.x + threadIdx.x;
    const int total = S * (NQ + NKV) * 32;
    if (idx >= total) return;
    int d = idx & 31;
    int rem = idx >> 5;
    int h = rem % (NQ + NKV);
    int s = rem / (NQ + NKV);

    float* row = qkv + (size_t)s * QKV_N + h * HD;
    float c0 = cosb[s * HD + d];
    float s0 = sinb[s * HD + d];
    float c1 = cosb[s * HD + d + 32];
    float s1 = sinb[s * HD + d + 32];
    float x0 = row[d];
    float x1 = row[d + 32];
    row[d]      = x0 * c0 - x1 * s0;
    row[d + 32] = x1 * c1 + x0 * s1;
}

// ---------------------------------------------------------------------------
// Sliding-window attention with sink logits (unchanged from R0).
// ---------------------------------------------------------------------------
__global__ __launch_bounds__(128) void attn_kernel(
    const float* __restrict__ qkv,
    const float* __restrict__ sinks,
    float* __restrict__ attn_out)
{
    __shared__ float sK[64 * HD];
    __shared__ float sV[64 * HD];

    const int h  = blockIdx.x;
    const int bi = blockIdx.y;
    const int n  = h >> 3;
    const int qi = threadIdx.x;

    float q[HD];
    {
        const float4* qsrc = (const float4*)(qkv + (size_t)(bi * Wwin + qi) * QKV_N + h * HD);
        #pragma unroll
        for (int i = 0; i < HD / 4; ++i) {
            float4 v = qsrc[i];
            q[i * 4 + 0] = v.x; q[i * 4 + 1] = v.y;
            q[i * 4 + 2] = v.z; q[i * 4 + 3] = v.w;
        }
    }

    float m = sinks[h];
    float l = 1.f;
    float o[HD];
    #pragma unroll
    for (int d = 0; d < HD; ++d) o[d] = 0.f;

    for (int sc = 0; sc < 4; ++sc) {
        const int c  = sc >> 1;
        const int kb = bi - 1 + c;
        if (kb < 0) continue;
        const int jb = (sc & 1) * 64;

        __syncthreads();
        for (int i = threadIdx.x; i < 64 * (HD / 4); i += 128) {
            int r  = i >> 4;
            int d4 = i & 15;
            size_t base = (size_t)(kb * Wwin + jb + r) * QKV_N + n * HD + d4 * 4;
            ((float4*)sK)[i] = *(const float4*)(qkv + base + NQ * HD);
            ((float4*)sV)[i] = *(const float4*)(qkv + base + (NQ + NKV) * HD);
        }
        __syncthreads();

        int jlo, jhi;
        if (c == 0) { jlo = qi + 1 - jb; if (jlo < 0) jlo = 0; jhi = 64; }
        else        { jlo = 0; jhi = qi + 1 - jb; if (jhi > 64) jhi = 64; if (jhi < 0) jhi = 0; }

        for (int j = jlo; j < jhi; ++j) {
            float sdot = 0.f;
            const float* krow = sK + j * HD;
            #pragma unroll
            for (int d = 0; d < HD; ++d) sdot += q[d] * krow[d];
            sdot *= SCALE;

            float mnew  = fmaxf(m, sdot);
            float corr  = __expf(m - mnew);
            float p     = __expf(sdot - mnew);
            l = l * corr + p;
            const float* vrow = sV + j * HD;
            #pragma unroll
            for (int d = 0; d < HD; ++d) o[d] = o[d] * corr + p * vrow[d];
            m = mnew;
        }
    }

    float inv = 1.f / l;
    float4* dst = (float4*)(attn_out + (size_t)(bi * Wwin + qi) * ATTN_N + h * HD);
    #pragma unroll
    for (int i = 0; i < HD / 4; ++i) {
        float4 v;
        v.x = o[i * 4 + 0] * inv; v.y = o[i * 4 + 1] * inv;
        v.z = o[i * 4 + 2] * inv; v.w = o[i * 4 + 3] * inv;
        dst[i] = v;
    }
}

// ---------------------------------------------------------------------------
// Launch
// ---------------------------------------------------------------------------
extern "C" void kernel_launch(void* const* d_in, const int* in_sizes, int n_in,
                              void* d_out, int out_size)
{
    const float* hidden = (const float*)d_in[0];
    const float* cosb   = (const float*)d_in[1];
    const float* sinb   = (const float*)d_in[2];
    const float* w_qkv  = (const float*)d_in[3];
    const float* b_qkv  = (const float*)d_in[4];
    const float* w_o    = (const float*)d_in[5];
    const float* b_o    = (const float*)d_in[6];
    const float* sinks  = (const float*)d_in[7];
    float* out = (float*)d_out;

    float *qkv, *attn;
    cudaGetSymbolAddress((void**)&qkv,  g_qkv);
    cudaGetSymbolAddress((void**)&attn, g_attn);

    // 1) QKV projection: [4096,2880] @ [2880,5120] + bias
    {
        dim3 grid(QKV_N / BN, S / BM);
        gemm_tf32_kernel<<<grid, 256>>>(hidden, w_qkv, b_qkv, qkv, S, QKV_N, Hdim);
    }
    // 2) RoPE
    {
        int total = S * (NQ + NKV) * 32;
        rope_kernel<<<(total + 255) / 256, 256>>>(qkv, cosb, sinb);
    }
    // 3) Attention
    {
        dim3 grid(NQ, S / Wwin);
        attn_kernel<<<grid, 128>>>(qkv, sinks, attn);
    }
    // 4) Output projection: [4096,4096] @ [4096,2880] + bias
    {
        dim3 grid(Hdim / BN, S / BM);
        gemm_tf32_kernel<<<grid, 256>>>(attn, w_o, b_o, out, S, Hdim, ATTN_N);
    }
}